// round 2
// baseline (speedup 1.0000x reference)
#include <cuda_runtime.h>
#include <cuda_bf16.h>

#define NTAGS 64
#define LOG2E 1.4426950408889634f
#define LN2   0.69314718055994531f

__device__ __forceinline__ float fast_ex2(float x) {
    float r; asm("ex2.approx.ftz.f32 %0, %1;" : "=f"(r) : "f"(x)); return r;
}
__device__ __forceinline__ float fast_lg2(float x) {
    float r; asm("lg2.approx.ftz.f32 %0, %1;" : "=f"(r) : "f"(x)); return r;
}
__device__ __forceinline__ void fma2(unsigned long long& d, unsigned long long a, unsigned long long b) {
    asm("fma.rn.f32x2 %0, %1, %2, %0;" : "+l"(d) : "l"(a), "l"(b));
}
__device__ __forceinline__ unsigned long long add2(unsigned long long a, unsigned long long b) {
    unsigned long long r; asm("add.rn.f32x2 %0, %1, %2;" : "=l"(r) : "l"(a), "l"(b)); return r;
}
__device__ __forceinline__ unsigned long long pack2(float x, float y) {
    unsigned long long r; asm("mov.b64 %0, {%1, %2};" : "=l"(r) : "f"(x), "f"(y)); return r;
}
__device__ __forceinline__ float2 unpack2(unsigned long long v) {
    float2 f; asm("mov.b64 {%0, %1}, %2;" : "=f"(f.x), "=f"(f.y) : "l"(v)); return f;
}

// CTA = 128 threads = 2 independent batch-pairs:
//   warps 0,1 (threads   0..63 ) -> pair 0 (batches 4b+0, 4b+1), SMSP 0,1
//   warps 2,3 (threads  64..127) -> pair 1 (batches 4b+2, 4b+3), SMSP 2,3
// Thread i of a group owns tag i. State kept in LINEAR domain:
//   P[i] = exp(score[i] - M);  step:  S = E*P ;  P' = fac * S
//   fac[i] = exp2(emit[i]*log2e - l2),  l2 = lg2(S[0]) lag-1 broadcast,
//   M' = M + ln2*l2. No transcendental on the per-step critical path.
__global__ __launch_bounds__(128, 1)
void crf_fwd_kernel(const float* __restrict__ h, const float* __restrict__ trans,
                    const int* __restrict__ lengths, float* __restrict__ out,
                    int B, int T)
{
    const int tid = threadIdx.x;
    const int g   = tid >> 6;          // pair group 0/1
    const int i   = tid & 63;          // tag index
    const int b0  = blockIdx.x * 4 + g * 2;
    const int b1  = b0 + 1;
    const int b0c = min(b0, B - 1);
    const int b1c = min(b1, B - 1);

    __shared__ __align__(16) unsigned long long pbuf[2][2][NTAGS]; // [group][buf][tag]
    __shared__ float2 l2buf[2][2];                                  // [group][buf]
    __shared__ float2 red[2][2];                                    // [group][warp]
    __shared__ int s_tmax;

    // Cache E[i][j] = exp(trans[i][j]) duplicated into f32x2 pairs (128 regs).
    unsigned long long rowp[NTAGS];
    const float4* trow = reinterpret_cast<const float4*>(trans + i * NTAGS);
    #pragma unroll
    for (int j4 = 0; j4 < NTAGS / 4; j4++) {
        float4 tv = trow[j4];
        float e0 = fast_ex2(tv.x * LOG2E);
        float e1 = fast_ex2(tv.y * LOG2E);
        float e2 = fast_ex2(tv.z * LOG2E);
        float e3 = fast_ex2(tv.w * LOG2E);
        rowp[4 * j4 + 0] = pack2(e0, e0);
        rowp[4 * j4 + 1] = pack2(e1, e1);
        rowp[4 * j4 + 2] = pack2(e2, e2);
        rowp[4 * j4 + 3] = pack2(e3, e3);
    }

    const int len0 = (b0 < B) ? lengths[b0] : 0;
    const int len1 = (b1 < B) ? lengths[b1] : 0;

    // CTA-uniform loop bound (max over the 4 batches of this CTA)
    if (tid == 0) {
        int tm = 0;
        #pragma unroll
        for (int k = 0; k < 4; k++) {
            int b = blockIdx.x * 4 + k;
            if (b < B) tm = max(tm, lengths[b]);
        }
        s_tmax = tm;
    }

    // init: START_TAG = N-2 -> score 0 -> p=1 ; others -10000 -> p=0
    float2 pc;
    pc.x = (i == NTAGS - 2) ? 1.0f : 0.0f;
    pc.y = pc.x;
    float m20 = 0.0f, m21 = 0.0f;      // M in log2 units, per batch

    pbuf[g][0][i] = pack2(pc.x, pc.y);
    if (i == 0) l2buf[g][0] = make_float2(0.0f, 0.0f);
    __syncthreads();
    const int tmax = s_tmax;

    const float* __restrict__ hp0 = h + (size_t)b0c * T * NTAGS + i;
    const float* __restrict__ hp1 = h + (size_t)b1c * T * NTAGS + i;

    // emissions prefetched 2 steps deep
    float ea0 = (tmax > 0) ? hp0[0] : 0.0f;
    float ea1 = (tmax > 0) ? hp1[0] : 0.0f;
    float eb0 = (tmax > 1) ? hp0[NTAGS] : 0.0f;
    float eb1 = (tmax > 1) ? hp1[NTAGS] : 0.0f;

    int buf = 0;
    for (int t = 0; t < tmax; t++) {
        float2 l2 = l2buf[g][buf];
        // fac for this step: off critical path (emissions already in regs)
        float fac0 = fast_ex2(fmaf(ea0, LOG2E, -l2.x));
        float fac1 = fast_ex2(fmaf(ea1, LOG2E, -l2.y));

        // dot(E_row_i, P): 32x LDS.128 broadcast + 64x FFMA2, 4 accumulators
        const ulonglong2* P = reinterpret_cast<const ulonglong2*>(pbuf[g][buf]);
        unsigned long long a0 = 0ull, a1 = 0ull, a2 = 0ull, a3 = 0ull;
        #pragma unroll
        for (int j = 0; j < NTAGS / 2; j += 2) {
            ulonglong2 q0 = P[j];
            ulonglong2 q1 = P[j + 1];
            fma2(a0, rowp[2 * j],     q0.x);
            fma2(a1, rowp[2 * j + 1], q0.y);
            fma2(a2, rowp[2 * j + 2], q1.x);
            fma2(a3, rowp[2 * j + 3], q1.y);
        }

        // prefetch emissions for t+2
        float ec0 = 0.0f, ec1 = 0.0f;
        if (t + 2 < tmax) { ec0 = hp0[2 * NTAGS]; ec1 = hp1[2 * NTAGS]; }
        hp0 += NTAGS; hp1 += NTAGS;

        float2 S = unpack2(add2(add2(a0, a1), add2(a2, a3)));

        // masked update in linear domain
        if (t < len0) { pc.x = fac0 * S.x; m20 += l2.x; }
        if (t < len1) { pc.y = fac1 * S.y; m21 += l2.y; }

        pbuf[g][buf ^ 1][i] = pack2(pc.x, pc.y);
        if (i == 0) l2buf[g][buf ^ 1] = make_float2(fast_lg2(S.x), fast_lg2(S.y));
        __syncthreads();

        ea0 = eb0; ea1 = eb1;
        eb0 = ec0; eb1 = ec1;
        buf ^= 1;
    }

    // Epilogue: score[i] = LN2*(m2 + lg2(p)) ; add END transition; exact LSE.
    float te = trans[(NTAGS - 1) * NTAGS + i];
    float x0 = LN2 * (m20 + fast_lg2(pc.x)) + te;
    float x1 = LN2 * (m21 + fast_lg2(pc.y)) + te;

    float m0 = x0, m1 = x1;
    #pragma unroll
    for (int o = 16; o > 0; o >>= 1) {
        m0 = fmaxf(m0, __shfl_xor_sync(0xffffffffu, m0, o));
        m1 = fmaxf(m1, __shfl_xor_sync(0xffffffffu, m1, o));
    }
    const int w = (tid >> 5) & 1;
    if ((i & 31) == 0) red[g][w] = make_float2(m0, m1);
    __syncthreads();
    m0 = fmaxf(red[g][0].x, red[g][1].x);
    m1 = fmaxf(red[g][0].y, red[g][1].y);

    float y0 = fast_ex2((x0 - m0) * LOG2E);
    float y1 = fast_ex2((x1 - m1) * LOG2E);
    #pragma unroll
    for (int o = 16; o > 0; o >>= 1) {
        y0 += __shfl_xor_sync(0xffffffffu, y0, o);
        y1 += __shfl_xor_sync(0xffffffffu, y1, o);
    }
    __syncthreads();   // red reuse
    if ((i & 31) == 0) red[g][w] = make_float2(y0, y1);
    __syncthreads();

    if (i == 0) {
        if (b0 < B) out[b0] = m0 + LN2 * fast_lg2(red[g][0].x + red[g][1].x);
        if (b1 < B) out[b1] = m1 + LN2 * fast_lg2(red[g][0].y + red[g][1].y);
    }
}

extern "C" void kernel_launch(void* const* d_in, const int* in_sizes, int n_in,
                              void* d_out, int out_size)
{
    const float* h       = (const float*)d_in[0];   // [B, T, N] f32
    const float* trans   = (const float*)d_in[1];   // [N, N]    f32
    const int*   lengths = (const int*)d_in[2];     // [B]       i32
    float*       out     = (float*)d_out;           // [B]       f32

    const int B = in_sizes[2];
    const int T = in_sizes[0] / (B * NTAGS);

    const int nblk = (B + 3) / 4;
    crf_fwd_kernel<<<nblk, 128>>>(h, trans, lengths, out, B, T);
}

// round 3
// speedup vs baseline: 1.9178x; 1.9178x over previous
#include <cuda_runtime.h>
#include <cuda_bf16.h>

#define NTAGS 64
#define LOG2E 1.4426950408889634f
#define LN2   0.69314718055994531f

__device__ __forceinline__ float fast_ex2(float x) {
    float r; asm("ex2.approx.ftz.f32 %0, %1;" : "=f"(r) : "f"(x)); return r;
}
__device__ __forceinline__ float fast_lg2(float x) {
    float r; asm("lg2.approx.ftz.f32 %0, %1;" : "=f"(r) : "f"(x)); return r;
}
__device__ __forceinline__ float fast_rcp(float x) {
    float r; asm("rcp.approx.ftz.f32 %0, %1;" : "=f"(r) : "f"(x)); return r;
}
__device__ __forceinline__ void fma2(unsigned long long& d, unsigned long long a, unsigned long long b) {
    asm("fma.rn.f32x2 %0, %1, %2, %0;" : "+l"(d) : "l"(a), "l"(b));
}
__device__ __forceinline__ unsigned long long add2(unsigned long long a, unsigned long long b) {
    unsigned long long r; asm("add.rn.f32x2 %0, %1, %2;" : "=l"(r) : "l"(a), "l"(b)); return r;
}
__device__ __forceinline__ unsigned long long pack2(float x, float y) {
    unsigned long long r; asm("mov.b64 %0, {%1, %2};" : "=l"(r) : "f"(x), "f"(y)); return r;
}
__device__ __forceinline__ float2 unpack2(unsigned long long v) {
    float2 f; asm("mov.b64 {%0, %1}, %2;" : "=f"(f.x), "=f"(f.y) : "l"(v)); return f;
}

// Named barrier over 64 threads (one group = 2 warps). Groups are DECOUPLED.
#define GROUP_BAR(id) asm volatile("bar.sync %0, 64;" :: "r"(id) : "memory")

// CTA = 128 threads = 2 independent batch-pairs (one per named barrier):
//   warps 0,1 (threads  0..63 ) -> group 0 -> SMSP 0,1
//   warps 2,3 (threads 64..127) -> group 1 -> SMSP 2,3
// grid = B/4 = 128 CTAs -> exactly one CTA per SM, one warp per SMSP.
//
// State in LINEAR domain: P[i] = exp(score[i] - M).
// Step: S = E*P ; P' = S * ex2(emit*log2e) * rcp(q) ; m2 += lg2(q), q = P[0].
// q is read by EVERY thread from its own first LDS of the P vector, so there
// is no cross-thread broadcast and no transcendental on the critical path.
__global__ __launch_bounds__(128, 1)
void crf_fwd_kernel(const float* __restrict__ h, const float* __restrict__ trans,
                    const int* __restrict__ lengths, float* __restrict__ out,
                    int B, int T)
{
    const int tid   = threadIdx.x;
    const int g     = tid >> 6;          // group 0/1
    const int i     = tid & 63;          // tag index
    const int barid = g + 1;             // named barrier id
    const int b0    = blockIdx.x * 4 + g * 2;
    const int b1    = b0 + 1;
    const int b0c   = min(b0, B - 1);
    const int b1c   = min(b1, B - 1);

    __shared__ __align__(16) unsigned long long pbuf[2][2][NTAGS]; // [group][buf][tag]
    __shared__ float2 red[2][2];                                    // [group][warp]

    // Cache E[i][j] = exp(trans[i][j]) duplicated into f32x2 pairs (128 regs).
    unsigned long long rowp[NTAGS];
    const float4* trow = reinterpret_cast<const float4*>(trans + i * NTAGS);
    #pragma unroll
    for (int j4 = 0; j4 < NTAGS / 4; j4++) {
        float4 tv = trow[j4];
        float e0 = fast_ex2(tv.x * LOG2E);
        float e1 = fast_ex2(tv.y * LOG2E);
        float e2 = fast_ex2(tv.z * LOG2E);
        float e3 = fast_ex2(tv.w * LOG2E);
        rowp[4 * j4 + 0] = pack2(e0, e0);
        rowp[4 * j4 + 1] = pack2(e1, e1);
        rowp[4 * j4 + 2] = pack2(e2, e2);
        rowp[4 * j4 + 3] = pack2(e3, e3);
    }

    const int len0 = (b0 < B) ? lengths[b0] : 0;
    const int len1 = (b1 < B) ? lengths[b1] : 0;
    const int tmax = max(len0, len1);    // group-local loop bound

    // init: START_TAG = N-2 -> score 0 -> p=1 ; others -> p=0
    float2 pc;
    pc.x = (i == NTAGS - 2) ? 1.0f : 0.0f;
    pc.y = pc.x;
    float m20 = 0.0f, m21 = 0.0f;        // accumulated normalizer, log2 units

    pbuf[g][0][i] = pack2(pc.x, pc.y);
    GROUP_BAR(barid);

    const float* __restrict__ hp0 = h + (size_t)b0c * T * NTAGS + i;
    const float* __restrict__ hp1 = h + (size_t)b1c * T * NTAGS + i;

    // emissions prefetched 2 steps deep
    float ea0 = (tmax > 0) ? hp0[0] : 0.0f;
    float ea1 = (tmax > 0) ? hp1[0] : 0.0f;
    float eb0 = (tmax > 1) ? hp0[NTAGS] : 0.0f;
    float eb1 = (tmax > 1) ? hp1[NTAGS] : 0.0f;

    int buf = 0;
    for (int t = 0; t < tmax; t++) {
        const ulonglong2* Pv = reinterpret_cast<const ulonglong2*>(pbuf[g][buf]);

        // First load carries the normalizer q = P[0] (per batch slot).
        ulonglong2 q0 = Pv[0];
        ulonglong2 q1 = Pv[1];
        float2 qq = unpack2(q0.x);
        float qx = (t == 0) ? 1.0f : qq.x;
        float qy = (t == 0) ? 1.0f : qq.y;

        unsigned long long a0 = 0ull, a1 = 0ull, a2 = 0ull, a3 = 0ull;
        fma2(a0, rowp[0], q0.x);
        fma2(a1, rowp[1], q0.y);
        fma2(a2, rowp[2], q1.x);
        fma2(a3, rowp[3], q1.y);

        // Normalizer math + emission exp: independent of the FFMA chain,
        // issues on MUFU while the dot streams.
        float rcx = fast_rcp(qx);
        float rcy = fast_rcp(qy);
        float l2x = fast_lg2(qx);
        float l2y = fast_lg2(qy);
        float rx  = fast_ex2(ea0 * LOG2E) * rcx;   // exp(emit)/q
        float ry  = fast_ex2(ea1 * LOG2E) * rcy;

        #pragma unroll
        for (int j = 2; j < NTAGS / 2; j += 2) {
            ulonglong2 v0 = Pv[j];
            ulonglong2 v1 = Pv[j + 1];
            fma2(a0, rowp[2 * j],     v0.x);
            fma2(a1, rowp[2 * j + 1], v0.y);
            fma2(a2, rowp[2 * j + 2], v1.x);
            fma2(a3, rowp[2 * j + 3], v1.y);
        }

        // prefetch emissions for t+2
        float ec0 = 0.0f, ec1 = 0.0f;
        if (t + 2 < tmax) { ec0 = hp0[2 * NTAGS]; ec1 = hp1[2 * NTAGS]; }
        hp0 += NTAGS; hp1 += NTAGS;

        float2 S = unpack2(add2(add2(a0, a1), add2(a2, a3)));

        // masked update in linear domain
        if (t < len0) { pc.x = S.x * rx; m20 += l2x; }
        if (t < len1) { pc.y = S.y * ry; m21 += l2y; }

        pbuf[g][buf ^ 1][i] = pack2(pc.x, pc.y);
        GROUP_BAR(barid);

        ea0 = eb0; ea1 = eb1;
        eb0 = ec0; eb1 = ec1;
        buf ^= 1;
    }

    // Epilogue: score[i] = LN2*(m2 + lg2(p)); add END transition; exact LSE.
    float te = trans[(NTAGS - 1) * NTAGS + i];
    float x0 = LN2 * (m20 + fast_lg2(pc.x)) + te;
    float x1 = LN2 * (m21 + fast_lg2(pc.y)) + te;

    float m0 = x0, m1 = x1;
    #pragma unroll
    for (int o = 16; o > 0; o >>= 1) {
        m0 = fmaxf(m0, __shfl_xor_sync(0xffffffffu, m0, o));
        m1 = fmaxf(m1, __shfl_xor_sync(0xffffffffu, m1, o));
    }
    const int w = (tid >> 5) & 1;
    if ((i & 31) == 0) red[g][w] = make_float2(m0, m1);
    GROUP_BAR(barid);
    m0 = fmaxf(red[g][0].x, red[g][1].x);
    m1 = fmaxf(red[g][0].y, red[g][1].y);

    float y0 = fast_ex2((x0 - m0) * LOG2E);
    float y1 = fast_ex2((x1 - m1) * LOG2E);
    #pragma unroll
    for (int o = 16; o > 0; o >>= 1) {
        y0 += __shfl_xor_sync(0xffffffffu, y0, o);
        y1 += __shfl_xor_sync(0xffffffffu, y1, o);
    }
    GROUP_BAR(barid);   // red reuse
    if ((i & 31) == 0) red[g][w] = make_float2(y0, y1);
    GROUP_BAR(barid);

    if (i == 0) {
        if (b0 < B) out[b0] = m0 + LN2 * fast_lg2(red[g][0].x + red[g][1].x);
        if (b1 < B) out[b1] = m1 + LN2 * fast_lg2(red[g][0].y + red[g][1].y);
    }
}

extern "C" void kernel_launch(void* const* d_in, const int* in_sizes, int n_in,
                              void* d_out, int out_size)
{
    const float* h       = (const float*)d_in[0];   // [B, T, N] f32
    const float* trans   = (const float*)d_in[1];   // [N, N]    f32
    const int*   lengths = (const int*)d_in[2];     // [B]       i32
    float*       out     = (float*)d_out;           // [B]       f32

    const int B = in_sizes[2];
    const int T = in_sizes[0] / (B * NTAGS);

    const int nblk = (B + 3) / 4;
    crf_fwd_kernel<<<nblk, 128>>>(h, trans, lengths, out, B, T);
}

// round 4
// speedup vs baseline: 1.9370x; 1.0100x over previous
#include <cuda_runtime.h>
#include <cuda_bf16.h>

#define NTAGS 64
#define LOG2E 1.4426950408889634f
#define LN2   0.69314718055994531f

__device__ __forceinline__ float fast_ex2(float x) {
    float r; asm("ex2.approx.ftz.f32 %0, %1;" : "=f"(r) : "f"(x)); return r;
}
__device__ __forceinline__ float fast_lg2(float x) {
    float r; asm("lg2.approx.ftz.f32 %0, %1;" : "=f"(r) : "f"(x)); return r;
}
__device__ __forceinline__ void fma2(unsigned long long& d, unsigned long long a, unsigned long long b) {
    asm("fma.rn.f32x2 %0, %1, %2, %0;" : "+l"(d) : "l"(a), "l"(b));
}
__device__ __forceinline__ unsigned long long add2(unsigned long long a, unsigned long long b) {
    unsigned long long r; asm("add.rn.f32x2 %0, %1, %2;" : "=l"(r) : "l"(a), "l"(b)); return r;
}
__device__ __forceinline__ unsigned long long pack2(float x, float y) {
    unsigned long long r; asm("mov.b64 %0, {%1, %2};" : "=l"(r) : "f"(x), "f"(y)); return r;
}
__device__ __forceinline__ float2 unpack2(unsigned long long v) {
    float2 f; asm("mov.b64 {%0, %1}, %2;" : "=f"(f.x), "=f"(f.y) : "l"(v)); return f;
}

// One CTA (128 threads) = ONE batch-pair (b0, b1). grid = B/2 = 256 -> 2 CTAs/SM,
// i.e. 2 warps per SMSP from INDEPENDENT chains: one hides the other's barrier/LDS
// latency. Warp w owns tags [16w, 16w+16); lane l handles tag 16w+(l&15), and
// half (l>>4) of the 64-term dot (32 FFMA2). Halves combine via shfl.bfly(16).
//
// Linear-domain state: P[i] = exp(score[i] - M); per step
//   S = E*P ;  P' = S * ex2(emit*log2e - lg2(q)) ;  m2 += lg2(q),  q = P[0].
// Fully branch-free inner loop.
__global__ __launch_bounds__(128, 2)
void crf_fwd_kernel(const float* __restrict__ h, const float* __restrict__ trans,
                    const int* __restrict__ lengths, float* __restrict__ out,
                    int B, int T)
{
    const int tid  = threadIdx.x;
    const int w    = tid >> 5;
    const int l    = tid & 31;
    const int half = l >> 4;             // which 32-term half of the dot
    const int tag  = w * 16 + (l & 15);  // output tag owned (stores done by half==0)
    const int j0   = half * 32;

    const int b0  = blockIdx.x * 2;
    const int b1  = b0 + 1;
    const int b1c = min(b1, B - 1);

    // halves padded 16B apart (u64 idx 0..31 and 34..65) -> disjoint banks
    __shared__ __align__(16) unsigned long long pbuf[2][68];
    __shared__ float2 red[4];

    // Cache E[tag][j0..j0+32) duplicated into f32x2 (32 u64 regs)
    unsigned long long rowp[32];
    const float4* trow = reinterpret_cast<const float4*>(trans + tag * NTAGS + j0);
    #pragma unroll
    for (int k = 0; k < 8; k++) {
        float4 tv = trow[k];
        float e0 = fast_ex2(tv.x * LOG2E);
        float e1 = fast_ex2(tv.y * LOG2E);
        float e2 = fast_ex2(tv.z * LOG2E);
        float e3 = fast_ex2(tv.w * LOG2E);
        rowp[4 * k + 0] = pack2(e0, e0);
        rowp[4 * k + 1] = pack2(e1, e1);
        rowp[4 * k + 2] = pack2(e2, e2);
        rowp[4 * k + 3] = pack2(e3, e3);
    }

    const int len0 = lengths[b0];
    const int len1 = lengths[b1c];
    const int tmax = max(len0, len1);

    const int sidx = tag + ((tag >> 5) << 1);   // store idx with 16B half-pad

    // init: START_TAG = N-2 -> p=1, others p=0
    float px = (tag == NTAGS - 2) ? 1.0f : 0.0f;
    float py = px;
    float m20 = 0.0f, m21 = 0.0f;               // normalizer accum (log2 units)

    if (half == 0) pbuf[0][sidx] = pack2(px, py);
    __syncthreads();

    const float* __restrict__ hp0 = h + (size_t)b0  * T * NTAGS + tag;
    const float* __restrict__ hp1 = h + (size_t)b1c * T * NTAGS + tag;

    float ea0 = hp0[0];
    float ea1 = hp1[0];
    const int o1 = (tmax > 1) ? NTAGS : 0;
    float eb0 = hp0[o1];
    float eb1 = hp1[o1];

    int buf = 0;
    for (int t = 0; t < tmax; t++) {
        const ulonglong2* Pv =
            reinterpret_cast<const ulonglong2*>(&pbuf[buf][half * 34]);

        ulonglong2 u0 = Pv[0];
        ulonglong2 u1 = Pv[1];
        float2 qq = unpack2(u0.x);              // q = P[0] (valid in half==0 lanes)
        float qx = (t == 0) ? 1.0f : qq.x;
        float qy = (t == 0) ? 1.0f : qq.y;

        unsigned long long a0 = 0ull, a1 = 0ull, a2 = 0ull, a3 = 0ull;
        fma2(a0, rowp[0], u0.x); fma2(a1, rowp[1], u0.y);
        fma2(a2, rowp[2], u1.x); fma2(a3, rowp[3], u1.y);

        // normalizer + emission factors on MUFU, overlapped with the dot
        float l2x = fast_lg2(qx);
        float l2y = fast_lg2(qy);
        float rx  = fast_ex2(fmaf(ea0, LOG2E, -l2x));
        float ry  = fast_ex2(fmaf(ea1, LOG2E, -l2y));

        #pragma unroll
        for (int k = 2; k < 16; k += 2) {
            ulonglong2 v0 = Pv[k];
            ulonglong2 v1 = Pv[k + 1];
            fma2(a0, rowp[2 * k + 0], v0.x); fma2(a1, rowp[2 * k + 1], v0.y);
            fma2(a2, rowp[2 * k + 2], v1.x); fma2(a3, rowp[2 * k + 3], v1.y);
        }

        // branch-free emission prefetch for t+2 (clamped offset, always in-bounds)
        const int onext = (t + 2 < tmax) ? 2 * NTAGS : 0;
        float ec0 = hp0[onext];
        float ec1 = hp1[onext];
        hp0 += NTAGS; hp1 += NTAGS;

        float2 sl = unpack2(add2(add2(a0, a1), add2(a2, a3)));
        float sx = sl.x + __shfl_xor_sync(0xffffffffu, sl.x, 16);
        float sy = sl.y + __shfl_xor_sync(0xffffffffu, sl.y, 16);

        // branch-free masked update (freeze past length)
        const bool k0 = t < len0;
        const bool k1 = t < len1;
        px   = k0 ? sx * rx : px;
        m20 += k0 ? l2x : 0.0f;
        py   = k1 ? sy * ry : py;
        m21 += k1 ? l2y : 0.0f;

        if (half == 0) pbuf[buf ^ 1][sidx] = pack2(px, py);
        __syncthreads();

        ea0 = eb0; ea1 = eb1;
        eb0 = ec0; eb1 = ec1;
        buf ^= 1;
    }

    // Epilogue: score[i] = LN2*(m2 + lg2(p)); add END transition row; exact LSE.
    float te = trans[(NTAGS - 1) * NTAGS + tag];
    float x0 = fmaf(LN2, m20 + fast_lg2(px), te);
    float x1 = fmaf(LN2, m21 + fast_lg2(py), te);
    if (half) { x0 = -1e30f; x1 = -1e30f; }     // duplicate-half lanes excluded

    float m0 = x0, m1 = x1;
    #pragma unroll
    for (int o = 16; o > 0; o >>= 1) {
        m0 = fmaxf(m0, __shfl_xor_sync(0xffffffffu, m0, o));
        m1 = fmaxf(m1, __shfl_xor_sync(0xffffffffu, m1, o));
    }
    if (l == 0) red[w] = make_float2(m0, m1);
    __syncthreads();
    m0 = fmaxf(fmaxf(red[0].x, red[1].x), fmaxf(red[2].x, red[3].x));
    m1 = fmaxf(fmaxf(red[0].y, red[1].y), fmaxf(red[2].y, red[3].y));

    float y0 = fast_ex2((x0 - m0) * LOG2E);     // -1e30 lanes contribute 0
    float y1 = fast_ex2((x1 - m1) * LOG2E);
    #pragma unroll
    for (int o = 16; o > 0; o >>= 1) {
        y0 += __shfl_xor_sync(0xffffffffu, y0, o);
        y1 += __shfl_xor_sync(0xffffffffu, y1, o);
    }
    __syncthreads();                            // red reuse
    if (l == 0) red[w] = make_float2(y0, y1);
    __syncthreads();

    if (tid == 0) {
        float s0 = (red[0].x + red[1].x) + (red[2].x + red[3].x);
        float s1 = (red[0].y + red[1].y) + (red[2].y + red[3].y);
        out[b0] = m0 + LN2 * fast_lg2(s0);
        if (b1 < B) out[b1] = m1 + LN2 * fast_lg2(s1);
    }
}

extern "C" void kernel_launch(void* const* d_in, const int* in_sizes, int n_in,
                              void* d_out, int out_size)
{
    const float* h       = (const float*)d_in[0];   // [B, T, N] f32
    const float* trans   = (const float*)d_in[1];   // [N, N]    f32
    const int*   lengths = (const int*)d_in[2];     // [B]       i32
    float*       out     = (float*)d_out;           // [B]       f32

    const int B = in_sizes[2];
    const int T = in_sizes[0] / (B * NTAGS);

    const int nblk = (B + 1) / 2;
    crf_fwd_kernel<<<nblk, 128>>>(h, trans, lengths, out, B, T);
}